// round 6
// baseline (speedup 1.0000x reference)
#include <cuda_runtime.h>

// DWT1D bior3.5, J=3, fused. R5: each row split into TWO half-row CTAs with
// halo recompute -> smem/CTA 58.2KB -> 2 CTAs/SM -> overlap the serial
// level chain across CTAs. 512 threads/CTA, swizzled smem (conflict-free).
//
// lo[n] = sum_l s[2n-10+l]*h0[l]  (zero extension everywhere; odd-pad == 0-ext)
// h1[i] = (i even ? -1 : +1) * h0[11-i]
//
// Output: [x0(=lo3) | hi1 | hi2 | hi3], rows concatenated per section.

#define N_IN   16384
#define O1     8197
#define O2     4104
#define O3     2057
#define NROWS  1024

// Uniform smem layout (floats), all sizes multiples of 32 (swizzle blocks):
//   sx  : 8320 (2080 float4 units)
//   sl1 : 4160
//   sl2 : 2080
#define SX_F    8320
#define SL1_F   4160
#define SL2_F   2080
#define SMEM_FLOATS (SX_F + SL1_F + SL2_F)     // 14560 -> 58240 bytes

#define OFF_X0  0
#define OFF_H1  ((size_t)NROWS * O3)
#define OFF_H2  (OFF_H1 + (size_t)NROWS * O1)
#define OFF_H3  (OFF_H2 + (size_t)NROWS * O2)

// XOR swizzle on 16-byte unit index (permutes within 32-float blocks).
__device__ __forceinline__ int swz4(int u) { return u ^ ((u >> 3) & 7); }
__device__ __forceinline__ int swzf(int f) {
    int u = f >> 2;
    return (swz4(u) << 2) | (f & 3);
}

// One analysis level over computed output range [g0, g0+4*ngroups).
// s: swizzled smem input, s[0] holds global index s_origin.
// Fast path: 5 aligned swizzled LDS.128 from local base bl = 2*g0-12-s_origin+8t
// (parameters chosen so bl%4==0; bl<0 only for the global left edge, where
// s_origin==0 and a checked scalar path applies).
// hi (and optional lo_gmem) stored to gmem only for n in assigned [a0, a1).
__device__ __forceinline__ void run_level(
    const float* __restrict__ s, int s_origin,
    int g0, int ngroups,
    const float* __restrict__ h0, const float* __restrict__ h1,
    float* __restrict__ lo_smem,     // local array, origin g0 (nullable)
    float* __restrict__ lo_gmem,     // global-indexed (nullable)
    float* __restrict__ hi_gmem,     // global-indexed
    int a0, int a1)
{
    const float4* s4 = (const float4*)s;
    const int bl0 = 2 * g0 - 12 - s_origin;
    for (int t = threadIdx.x; t < ngroups; t += blockDim.x) {
        const int n0 = g0 + 4 * t;
        const int bl = bl0 + 8 * t;
        float lo[4] = {0.f, 0.f, 0.f, 0.f};
        float hi[4] = {0.f, 0.f, 0.f, 0.f};

        if (bl >= 0) {
            const int ub = bl >> 2;
            float v[20];
            #pragma unroll
            for (int q = 0; q < 5; q++) {
                float4 a = s4[swz4(ub + q)];
                v[4 * q + 0] = a.x; v[4 * q + 1] = a.y;
                v[4 * q + 2] = a.z; v[4 * q + 3] = a.w;
            }
            #pragma unroll
            for (int j = 0; j < 4; j++) {
                #pragma unroll
                for (int l = 0; l < 12; l++) {
                    const float xv = v[2 + 2 * j + l];
                    lo[j] += xv * h0[l];
                    hi[j] += xv * h1[l];
                }
            }
        } else {
            // global left edge: s_origin == 0, only idx>=0 needs checking
            #pragma unroll
            for (int j = 0; j < 4; j++) {
                const int n = n0 + j;
                #pragma unroll
                for (int l = 0; l < 12; l++) {
                    const int idx = 2 * n - 10 + l;
                    if (idx >= 0) {
                        const float xv = s[swzf(idx)];
                        lo[j] += xv * h0[l];
                        hi[j] += xv * h1[l];
                    }
                }
            }
        }

        if (lo_smem)
            ((float4*)lo_smem)[swz4(t)] = make_float4(lo[0], lo[1], lo[2], lo[3]);

        #pragma unroll
        for (int j = 0; j < 4; j++) {
            const int n = n0 + j;
            if (n >= a0 && n < a1) {
                hi_gmem[n] = hi[j];
                if (lo_gmem) lo_gmem[n] = lo[j];
            }
        }
    }
}

__global__ void __launch_bounds__(512, 2)
dwt1d_split_kernel(const float* __restrict__ x,
                   const float* __restrict__ hac,
                   float* __restrict__ out)
{
    extern __shared__ float sm[];
    float* sx  = sm;
    float* sl1 = sm + SX_F;
    float* sl2 = sm + SX_F + SL1_F;

    const int half = blockIdx.x & 1;
    const int row  = blockIdx.x >> 1;

    // Per-half ranges (all g0 multiples of 4; half1 bases give bl0 == 0):
    //           half0                 half1
    // x slice:  [0,8256)              [8172,16464) (zeros past 16384)
    // lo1:      [0,4128)              [4092,8232)  (phantoms >=8197 are 0)
    // lo2:      [0,2064)              [2052,4116)  (phantoms >=4104 are 0)
    // lo3 out:  [0,1032)              [1032,2057)
    const int xg0   = half ? 8172 : 0;
    const int g0_1  = half ? 4092 : 0;
    const int ng_1  = half ? 1035 : 1032;
    const int a0_1  = half ? 4128 : 0;
    const int a1_1  = half ? O1   : 4128;
    const int g0_2  = half ? 2052 : 0;
    const int ng_2  = 516;
    const int a0_2  = half ? 2064 : 0;
    const int a1_2  = half ? O2   : 2064;
    const int g0_3  = half ? 1032 : 0;
    const int ng_3  = half ? 257  : 258;
    const int a0_3  = half ? 1032 : 0;
    const int a1_3  = half ? O3   : 1032;

    // Filters -> registers.
    float h0[12], h1[12];
    #pragma unroll
    for (int i = 0; i < 12; i++) h0[i] = __ldg(hac + i);
    #pragma unroll
    for (int i = 0; i < 12; i++)
        h1[i] = ((i & 1) ? 1.0f : -1.0f) * h0[11 - i];

    // Load x slice into swizzled smem (float4; xg0 is 16B-aligned).
    {
        const float4* in4 = (const float4*)(x + (size_t)row * N_IN + xg0);
        float4* sx4 = (float4*)sx;
        const int ncopy = half ? 2053 : 2064;     // units of valid gmem data
        for (int u = threadIdx.x; u < ncopy; u += blockDim.x)
            sx4[swz4(u)] = in4[u];
        // zero tail units [ncopy, 2080)
        for (int u = ncopy + threadIdx.x; u < SX_F / 4; u += blockDim.x)
            sx4[swz4(u)] = make_float4(0.f, 0.f, 0.f, 0.f);
        // zero lo2 pad units [516, 520) (read as zeros by half1 level 3)
        if (threadIdx.x < 4)
            ((float4*)sl2)[swz4(516 + threadIdx.x)] = make_float4(0.f, 0.f, 0.f, 0.f);
    }
    __syncthreads();

    float* hi1 = out + OFF_H1 + (size_t)row * O1;
    float* hi2 = out + OFF_H2 + (size_t)row * O2;
    float* hi3 = out + OFF_H3 + (size_t)row * O3;
    float* x0  = out + OFF_X0 + (size_t)row * O3;

    run_level(sx,  xg0,  g0_1, ng_1, h0, h1, sl1,     nullptr, hi1, a0_1, a1_1);
    __syncthreads();
    run_level(sl1, g0_1, g0_2, ng_2, h0, h1, sl2,     nullptr, hi2, a0_2, a1_2);
    __syncthreads();
    run_level(sl2, g0_2, g0_3, ng_3, h0, h1, nullptr, x0,      hi3, a0_3, a1_3);
}

extern "C" void kernel_launch(void* const* d_in, const int* in_sizes, int n_in,
                              void* d_out, int out_size)
{
    int xi = 0, hi = 1;
    if (n_in >= 2 && in_sizes[0] == 12) { xi = 1; hi = 0; }

    const float* x   = (const float*)d_in[xi];
    const float* hac = (const float*)d_in[hi];
    float* out = (float*)d_out;

    const size_t smem_bytes = (size_t)SMEM_FLOATS * sizeof(float);   // 58240
    cudaFuncSetAttribute(dwt1d_split_kernel,
                         cudaFuncAttributeMaxDynamicSharedMemorySize,
                         (int)smem_bytes);
    cudaFuncSetAttribute(dwt1d_split_kernel,
                         cudaFuncAttributePreferredSharedMemoryCarveout, 100);

    dwt1d_split_kernel<<<2 * NROWS, 512, smem_bytes>>>(x, hac, out);
}

// round 8
// speedup vs baseline: 1.9825x; 1.9825x over previous
#include <cuda_runtime.h>

// DWT1D bior3.5, J=3, fused. R7 = R6 re-bench (infra failed) + edge-path cleanup.
//  - level 1 reads x straight from gmem (coalesced LDG.128, L1 serves overlap)
//  - smem holds only lo1 (8208 f) + lo2 (4116 f) = 49.3 KB -> 4 CTAs/SM
//  - 2 output pairs per thread: natural even float-pairs => packed fma.rn.f32x2
//    (24 FFMA2 + 4 FADD per group instead of 96 FFMA), conflict-free smem
//    in plain layout (16B lane stride), no swizzle, no extra ALU
//
// lo[n] = sum_l s[2n-10+l]*h0[l]  (zero extension; odd-pad == zero extension)
// h1[i] = (i even ? -1 : +1) * h0[11-i]
// Output: [x0(=lo3) | hi1 | hi2 | hi3], rows concatenated per section.

#define N_IN   16384
#define O1     8197
#define O2     4104
#define O3     2057
#define NROWS  1024

#define SL1_F  8208      // valid [0,8197), zeros [8197,8208)
#define SL2_F  4116      // valid [0,4104), zeros [4104,4116)
#define SMEM_FLOATS (SL1_F + SL2_F)          // 12324 floats = 49296 B

#define OFF_X0  0
#define OFF_H1  ((size_t)NROWS * O3)
#define OFF_H2  (OFF_H1 + (size_t)NROWS * O1)
#define OFF_H3  (OFF_H2 + (size_t)NROWS * O2)

typedef unsigned long long u64;

__device__ __forceinline__ u64 ffma2(u64 a, u64 b, u64 c) {
    u64 d;
    asm("fma.rn.f32x2 %0, %1, %2, %3;" : "=l"(d) : "l"(a), "l"(b), "l"(c));
    return d;
}
__device__ __forceinline__ u64 pack2(float x, float y) {
    u64 r;
    asm("mov.b64 %0, {%1, %2};" : "=l"(r) : "f"(x), "f"(y));
    return r;
}
__device__ __forceinline__ void unpack2(u64 a, float& x, float& y) {
    asm("mov.b64 {%0, %1}, %2;" : "=f"(x), "=f"(y) : "l"(a));
}
__device__ __forceinline__ float hsum2(u64 a) {
    float x, y;
    unpack2(a, x, y);
    return x + y;
}

// One analysis level. Thread t computes outputs n = 2t, 2t+1 from
// src[4t-12 .. 4t+3], loaded as 4x 128-bit (8 natural even pairs vp[0..7]).
//   lo(2t)   = sum_m vp[1+m] . ch0[m]   (packed, then horizontal add)
//   hi(2t)   = sum_m vp[1+m] . ch1[m]
//   lo(2t+1) = sum_m vp[2+m] . ch0[m]
//   hi(2t+1) = sum_m vp[2+m] . ch1[m]
// Fast path valid for 3 <= t <= tmax_fast; outside that, masked scalar path
// (zero extension via 0 <= idx < src_valid; smem pads are zero-filled so the
// upper mask is only load-safety, not semantics).
__device__ __forceinline__ void run_level(
    const float* __restrict__ src, int src_valid,
    int M, int G, int tmax_fast,
    const u64* __restrict__ ch0, const u64* __restrict__ ch1,
    float* __restrict__ lo_smem,     // nullable
    float* __restrict__ lo_gmem,     // nullable
    float* __restrict__ hi_gmem)
{
    for (int t = threadIdx.x; t < G; t += blockDim.x) {
        const int n0 = 2 * t;
        float lo0, lo1, hi0, hi1;

        if (t >= 3 && t <= tmax_fast) {
            const ulonglong2* s2 = (const ulonglong2*)src;
            u64 vp[8];
            #pragma unroll
            for (int q = 0; q < 4; q++) {
                ulonglong2 a = s2[t - 3 + q];
                vp[2 * q]     = a.x;
                vp[2 * q + 1] = a.y;
            }
            u64 a0 = 0ull, b0 = 0ull, a1 = 0ull, b1 = 0ull;
            #pragma unroll
            for (int m = 0; m < 6; m++) {
                a0 = ffma2(vp[1 + m], ch0[m], a0);
                b0 = ffma2(vp[1 + m], ch1[m], b0);
                a1 = ffma2(vp[2 + m], ch0[m], a1);
                b1 = ffma2(vp[2 + m], ch1[m], b1);
            }
            lo0 = hsum2(a0); hi0 = hsum2(b0);
            lo1 = hsum2(a1); hi1 = hsum2(b1);
        } else {
            // cold edge path: unpack scalar filters from resident packed regs
            float h0s[12], h1s[12];
            #pragma unroll
            for (int m = 0; m < 6; m++) {
                unpack2(ch0[m], h0s[2 * m], h0s[2 * m + 1]);
                unpack2(ch1[m], h1s[2 * m], h1s[2 * m + 1]);
            }
            float lv[2] = {0.f, 0.f}, hv[2] = {0.f, 0.f};
            #pragma unroll
            for (int j = 0; j < 2; j++) {
                const int n = n0 + j;
                #pragma unroll
                for (int l = 0; l < 12; l++) {
                    const int idx = 2 * n - 10 + l;
                    if (idx >= 0 && idx < src_valid) {
                        const float xv = src[idx];
                        lv[j] += xv * h0s[l];
                        hv[j] += xv * h1s[l];
                    }
                }
            }
            lo0 = lv[0]; hi0 = hv[0]; lo1 = lv[1]; hi1 = hv[1];
        }

        const bool ok1 = (n0 + 1 < M);
        if (lo_smem) {
            if (ok1) ((float2*)lo_smem)[t] = make_float2(lo0, lo1);
            else if (n0 < M) lo_smem[n0] = lo0;
        }
        if (n0 < M) {
            hi_gmem[n0] = hi0;
            if (lo_gmem) lo_gmem[n0] = lo0;
        }
        if (ok1) {
            hi_gmem[n0 + 1] = hi1;
            if (lo_gmem) lo_gmem[n0 + 1] = lo1;
        }
    }
}

__global__ void __launch_bounds__(256, 4)
dwt1d_r7_kernel(const float* __restrict__ x,
                const float* __restrict__ hac,
                float* __restrict__ out)
{
    extern __shared__ float sm[];
    float* sl1 = sm;
    float* sl2 = sm + SL1_F;

    const int row = blockIdx.x;
    const float* xr = x + (size_t)row * N_IN;

    // Packed coefficient pairs: ch0[m]=(h0[2m],h0[2m+1]), ch1 likewise for h1.
    u64 ch0[6], ch1[6];
    {
        float h0s[12], h1s[12];
        #pragma unroll
        for (int i = 0; i < 12; i++) h0s[i] = __ldg(hac + i);
        #pragma unroll
        for (int i = 0; i < 12; i++)
            h1s[i] = ((i & 1) ? 1.0f : -1.0f) * h0s[11 - i];
        #pragma unroll
        for (int m = 0; m < 6; m++) {
            ch0[m] = pack2(h0s[2 * m], h0s[2 * m + 1]);
            ch1[m] = pack2(h1s[2 * m], h1s[2 * m + 1]);
        }
    }

    // Zero pads (read as zero-extension by the next level; never overwritten:
    // level1 stores only n<8197, level2 only n<4104).
    if (threadIdx.x < 11)       sl1[O1 + threadIdx.x] = 0.f;        // 8197..8207
    else if (threadIdx.x < 23)  sl2[O2 + (threadIdx.x - 11)] = 0.f; // 4104..4115

    float* hi1 = out + OFF_H1 + (size_t)row * O1;
    float* hi2 = out + OFF_H2 + (size_t)row * O2;
    float* hi3 = out + OFF_H3 + (size_t)row * O3;
    float* x0  = out + OFF_X0 + (size_t)row * O3;

    // Level 1: gmem -> (sl1, hi1). G=4099; fast path needs src[4t+3]<=16383
    // => t<=4095; t=4096..4098 handle the right zero-extension scalar.
    run_level(xr, N_IN, O1, 4099, 4095, ch0, ch1, sl1, nullptr, hi1);
    __syncthreads();
    // Level 2: sl1 -> (sl2, hi2). G=2052; max fast read 4*2051+3=8207 < 8208.
    run_level(sl1, SL1_F, O2, 2052, 2051, ch0, ch1, sl2, nullptr, hi2);
    __syncthreads();
    // Level 3: sl2 -> (x0, hi3). G=1029; max fast read 4*1028+3=4115 < 4116.
    run_level(sl2, SL2_F, O3, 1029, 1028, ch0, ch1, nullptr, x0, hi3);
}

extern "C" void kernel_launch(void* const* d_in, const int* in_sizes, int n_in,
                              void* d_out, int out_size)
{
    int xi = 0, hi = 1;
    if (n_in >= 2 && in_sizes[0] == 12) { xi = 1; hi = 0; }

    const float* x   = (const float*)d_in[xi];
    const float* hac = (const float*)d_in[hi];
    float* out = (float*)d_out;

    const size_t smem_bytes = (size_t)SMEM_FLOATS * sizeof(float);   // 49296
    cudaFuncSetAttribute(dwt1d_r7_kernel,
                         cudaFuncAttributeMaxDynamicSharedMemorySize,
                         (int)smem_bytes);
    cudaFuncSetAttribute(dwt1d_r7_kernel,
                         cudaFuncAttributePreferredSharedMemoryCarveout, 100);

    dwt1d_r7_kernel<<<NROWS, 256, smem_bytes>>>(x, hac, out);
}

// round 11
// speedup vs baseline: 2.0149x; 1.0163x over previous
#include <cuda_runtime.h>

// DWT1D bior3.5, J=3, fused. R8 = R7 + wider level-1 (4 outputs/thread,
// 5xLDG.128 per 4 outputs instead of 8) + alignment-checked vector stores.
//  - level 1 reads x straight from gmem; levels 2/3 from smem at 2/thread
//    (16B lane stride = conflict-free, no swizzle)
//  - smem holds only lo1 (8208 f) + lo2 (4116 f) = 49.3 KB -> 4 CTAs/SM
//  - packed fma.rn.f32x2 throughout (2 MACs/instruction)
//
// lo[n] = sum_l s[2n-10+l]*h0[l]  (zero extension; odd-pad == zero extension)
// h1[i] = (i even ? -1 : +1) * h0[11-i]
// Output: [x0(=lo3) | hi1 | hi2 | hi3], rows concatenated per section.

#define N_IN   16384
#define O1     8197
#define O2     4104
#define O3     2057
#define NROWS  1024

#define SL1_F  8208      // valid [0,8197), zeros [8197,8208)
#define SL2_F  4116      // valid [0,4104), zeros [4104,4116)
#define SMEM_FLOATS (SL1_F + SL2_F)          // 12324 floats = 49296 B

#define OFF_X0  0
#define OFF_H1  ((size_t)NROWS * O3)
#define OFF_H2  (OFF_H1 + (size_t)NROWS * O1)
#define OFF_H3  (OFF_H2 + (size_t)NROWS * O2)

typedef unsigned long long u64;

__device__ __forceinline__ u64 ffma2(u64 a, u64 b, u64 c) {
    u64 d;
    asm("fma.rn.f32x2 %0, %1, %2, %3;" : "=l"(d) : "l"(a), "l"(b), "l"(c));
    return d;
}
__device__ __forceinline__ u64 pack2(float x, float y) {
    u64 r;
    asm("mov.b64 %0, {%1, %2};" : "=l"(r) : "f"(x), "f"(y));
    return r;
}
__device__ __forceinline__ void unpack2(u64 a, float& x, float& y) {
    asm("mov.b64 {%0, %1}, %2;" : "=f"(x), "=f"(y) : "l"(a));
}
__device__ __forceinline__ float hsum2(u64 a) {
    float x, y;
    unpack2(a, x, y);
    return x + y;
}

// Alignment-checked vector stores. The predicate is uniform across the warp
// (base alignment is per-row, offsets are multiples of the vector width).
__device__ __forceinline__ void store2(float* p, float a, float b) {
    if ((((size_t)p) & 7) == 0) *(float2*)p = make_float2(a, b);
    else { p[0] = a; p[1] = b; }
}
__device__ __forceinline__ void store4(float* p, float a, float b, float c, float d) {
    if ((((size_t)p) & 15) == 0) *(float4*)p = make_float4(a, b, c, d);
    else { p[0] = a; p[1] = b; p[2] = c; p[3] = d; }
}

// ---------------- Level 1: gmem -> (sl1 smem, hi1 gmem), 4 outputs/thread ---
// Thread t computes n = 4t..4t+3 from x[8t-12 .. 8t+7] (10 natural even
// pairs via 5x 128-bit loads). Output j uses pairs vp[j+1 .. j+6].
__device__ __forceinline__ void level1(
    const float* __restrict__ xr,
    const u64* __restrict__ ch0, const u64* __restrict__ ch1,
    float* __restrict__ sl1, float* __restrict__ hi1)
{
    const int G = 2050;                       // ceil(8197/4)
    for (int t = threadIdx.x; t < G; t += blockDim.x) {
        const int n0 = 4 * t;
        float lo[4], hi[4];

        if (t >= 2 && t <= 2047) {
            const ulonglong2* s2 = (const ulonglong2*)xr;
            u64 vp[10];
            #pragma unroll
            for (int q = 0; q < 5; q++) {
                ulonglong2 a = s2[2 * t - 3 + q];
                vp[2 * q]     = a.x;
                vp[2 * q + 1] = a.y;
            }
            #pragma unroll
            for (int j = 0; j < 4; j++) {
                u64 a = 0ull, b = 0ull;
                #pragma unroll
                for (int m = 0; m < 6; m++) {
                    a = ffma2(vp[j + 1 + m], ch0[m], a);
                    b = ffma2(vp[j + 1 + m], ch1[m], b);
                }
                lo[j] = hsum2(a); hi[j] = hsum2(b);
            }
        } else {
            float h0s[12], h1s[12];
            #pragma unroll
            for (int m = 0; m < 6; m++) {
                unpack2(ch0[m], h0s[2 * m], h0s[2 * m + 1]);
                unpack2(ch1[m], h1s[2 * m], h1s[2 * m + 1]);
            }
            #pragma unroll
            for (int j = 0; j < 4; j++) {
                const int n = n0 + j;
                float lv = 0.f, hv = 0.f;
                #pragma unroll
                for (int l = 0; l < 12; l++) {
                    const int idx = 2 * n - 10 + l;
                    if (idx >= 0 && idx < N_IN) {
                        const float xv = xr[idx];
                        lv += xv * h0s[l];
                        hv += xv * h1s[l];
                    }
                }
                lo[j] = lv; hi[j] = hv;       // exact 0 beyond O1 (all-zero window)
            }
        }

        // smem lo: always-aligned float4; t=2049 writes [8196..8199] into the
        // zero pad with exact zeros for n>=O1 — safe.
        ((float4*)sl1)[t] = make_float4(lo[0], lo[1], lo[2], lo[3]);

        if (t < 2049) {
            store4(hi1 + n0, hi[0], hi[1], hi[2], hi[3]);
        } else {                               // n0 = 8196, only j=0 valid
            hi1[n0] = hi[0];
        }
    }
}

// ------------- Levels 2/3: smem -> smem/gmem, 2 outputs/thread (R7 scheme) --
__device__ __forceinline__ void run_level(
    const float* __restrict__ src, int src_valid,
    int M, int G, int tmax_fast,
    const u64* __restrict__ ch0, const u64* __restrict__ ch1,
    float* __restrict__ lo_smem,     // nullable
    float* __restrict__ lo_gmem,     // nullable
    float* __restrict__ hi_gmem)
{
    for (int t = threadIdx.x; t < G; t += blockDim.x) {
        const int n0 = 2 * t;
        float lo0, lo1, hi0, hi1;

        if (t >= 3 && t <= tmax_fast) {
            const ulonglong2* s2 = (const ulonglong2*)src;
            u64 vp[8];
            #pragma unroll
            for (int q = 0; q < 4; q++) {
                ulonglong2 a = s2[t - 3 + q];
                vp[2 * q]     = a.x;
                vp[2 * q + 1] = a.y;
            }
            u64 a0 = 0ull, b0 = 0ull, a1 = 0ull, b1 = 0ull;
            #pragma unroll
            for (int m = 0; m < 6; m++) {
                a0 = ffma2(vp[1 + m], ch0[m], a0);
                b0 = ffma2(vp[1 + m], ch1[m], b0);
                a1 = ffma2(vp[2 + m], ch0[m], a1);
                b1 = ffma2(vp[2 + m], ch1[m], b1);
            }
            lo0 = hsum2(a0); hi0 = hsum2(b0);
            lo1 = hsum2(a1); hi1 = hsum2(b1);
        } else {
            float h0s[12], h1s[12];
            #pragma unroll
            for (int m = 0; m < 6; m++) {
                unpack2(ch0[m], h0s[2 * m], h0s[2 * m + 1]);
                unpack2(ch1[m], h1s[2 * m], h1s[2 * m + 1]);
            }
            float lv[2] = {0.f, 0.f}, hv[2] = {0.f, 0.f};
            #pragma unroll
            for (int j = 0; j < 2; j++) {
                const int n = n0 + j;
                #pragma unroll
                for (int l = 0; l < 12; l++) {
                    const int idx = 2 * n - 10 + l;
                    if (idx >= 0 && idx < src_valid) {
                        const float xv = src[idx];
                        lv[j] += xv * h0s[l];
                        hv[j] += xv * h1s[l];
                    }
                }
            }
            lo0 = lv[0]; hi0 = hv[0]; lo1 = lv[1]; hi1 = hv[1];
        }

        const bool ok1 = (n0 + 1 < M);
        if (lo_smem) {
            if (ok1) ((float2*)lo_smem)[t] = make_float2(lo0, lo1);
            else if (n0 < M) lo_smem[n0] = lo0;
        }
        if (ok1) {
            store2(hi_gmem + n0, hi0, hi1);
            if (lo_gmem) store2(lo_gmem + n0, lo0, lo1);
        } else if (n0 < M) {
            hi_gmem[n0] = hi0;
            if (lo_gmem) lo_gmem[n0] = lo0;
        }
    }
}

__global__ void __launch_bounds__(256, 4)
dwt1d_r8_kernel(const float* __restrict__ x,
                const float* __restrict__ hac,
                float* __restrict__ out)
{
    extern __shared__ float sm[];
    float* sl1 = sm;
    float* sl2 = sm + SL1_F;

    const int row = blockIdx.x;
    const float* xr = x + (size_t)row * N_IN;

    // Packed coefficient pairs: ch0[m]=(h0[2m],h0[2m+1]), ch1 likewise for h1.
    u64 ch0[6], ch1[6];
    {
        float h0s[12], h1s[12];
        #pragma unroll
        for (int i = 0; i < 12; i++) h0s[i] = __ldg(hac + i);
        #pragma unroll
        for (int i = 0; i < 12; i++)
            h1s[i] = ((i & 1) ? 1.0f : -1.0f) * h0s[11 - i];
        #pragma unroll
        for (int m = 0; m < 6; m++) {
            ch0[m] = pack2(h0s[2 * m], h0s[2 * m + 1]);
            ch1[m] = pack2(h1s[2 * m], h1s[2 * m + 1]);
        }
    }

    // Zero pads (zero-extension for the next level's fast path).
    if (threadIdx.x < 11)       sl1[O1 + threadIdx.x] = 0.f;        // 8197..8207
    else if (threadIdx.x < 23)  sl2[O2 + (threadIdx.x - 11)] = 0.f; // 4104..4115

    float* hi1 = out + OFF_H1 + (size_t)row * O1;
    float* hi2 = out + OFF_H2 + (size_t)row * O2;
    float* hi3 = out + OFF_H3 + (size_t)row * O3;
    float* x0  = out + OFF_X0 + (size_t)row * O3;

    // Level 1: gmem -> (sl1, hi1), 4 outputs/thread.
    level1(xr, ch0, ch1, sl1, hi1);
    __syncthreads();
    // Level 2: sl1 -> (sl2, hi2). G=2052; max fast read 4*2051+3=8207 < 8208.
    run_level(sl1, SL1_F, O2, 2052, 2051, ch0, ch1, sl2, nullptr, hi2);
    __syncthreads();
    // Level 3: sl2 -> (x0, hi3). G=1029; max fast read 4*1028+3=4115 < 4116.
    run_level(sl2, SL2_F, O3, 1029, 1028, ch0, ch1, nullptr, x0, hi3);
}

extern "C" void kernel_launch(void* const* d_in, const int* in_sizes, int n_in,
                              void* d_out, int out_size)
{
    int xi = 0, hi = 1;
    if (n_in >= 2 && in_sizes[0] == 12) { xi = 1; hi = 0; }

    const float* x   = (const float*)d_in[xi];
    const float* hac = (const float*)d_in[hi];
    float* out = (float*)d_out;

    const size_t smem_bytes = (size_t)SMEM_FLOATS * sizeof(float);   // 49296
    cudaFuncSetAttribute(dwt1d_r8_kernel,
                         cudaFuncAttributeMaxDynamicSharedMemorySize,
                         (int)smem_bytes);
    cudaFuncSetAttribute(dwt1d_r8_kernel,
                         cudaFuncAttributePreferredSharedMemoryCarveout, 100);

    dwt1d_r8_kernel<<<NROWS, 256, smem_bytes>>>(x, hac, out);
}